// round 4
// baseline (speedup 1.0000x reference)
#include <cuda_runtime.h>
#include <math.h>

#define HW     1024
#define BUFW   128
#define BUFH   152
#define TILEH  128
#define TILEW  104
#define HALO   12
#define NT     512
#define NCT    10
#define NRT    8
#define NTILES 80
#define OTW    104
#define INFV   __int_as_float(0x7f800000)
#define NEGB   (-1.0e30f)

// per-tile partials: [z][img][tile][{sum_skel, sum_skel*other}]
__device__ float g_part[2*32*NTILES*2];

__device__ __forceinline__ float sigmoidf_(float x){ return 1.0f/(1.0f+__expf(-x)); }
__device__ __forceinline__ float4 ld4s(const float* p){ return *reinterpret_cast<const float4*>(p); }
__device__ __forceinline__ void   st4s(float* p, float4 v){ *reinterpret_cast<float4*>(p) = v; }

__device__ __forceinline__ float4 ldrow(const float* IMG, int r, int c4){
    if ((unsigned)r < (unsigned)BUFH) return ld4s(IMG + r*BUFW + c4);
    return make_float4(INFV,INFV,INFV,INFV);
}

__global__ __launch_bounds__(NT, 1)
void cldice_main(const float* __restrict__ logits, const float* __restrict__ targets){
    extern __shared__ float sm[];
    float* A  = sm;
    float* B  = sm +   BUFH*BUFW;
    float* OT = sm + 2*BUFH*BUFW;

    const int tid  = threadIdx.x;
    const int lane = tid & 31;
    const int w    = tid >> 5;                 // 16 warps
    const int tile = blockIdx.x;               // 0..79
    const int img  = blockIdx.y;               // 0..31
    const int z    = blockIdx.z;               // 0: skel(pred), 1: skel(gt)
    const int tr0  = (tile / NCT) * TILEH;
    const int tc0  = (tile % NCT) * TILEW;
    const int base_r = tr0 - HALO;
    const int base_c = tc0 - HALO;
    const size_t ioff = (size_t)img * (HW*HW);
    const float* src = (z==0 ? logits : targets) + ioff;
    const float* oth = (z==0 ? targets : logits) + ioff;

    const int c4  = 4*lane;
    const int gc0 = base_c + c4;
    const bool ck0 = (unsigned)(gc0+0) < (unsigned)HW;
    const bool ck1 = (unsigned)(gc0+1) < (unsigned)HW;
    const bool ck2 = (unsigned)(gc0+2) < (unsigned)HW;
    const bool ck3 = (unsigned)(gc0+3) < (unsigned)HW;

    // ---- load A (tile + halo, +INF outside image) ----
    for (int r = w; r < BUFH; r += 16){
        int gr = base_r + r;
        float4 v = make_float4(INFV,INFV,INFV,INFV);
        if ((unsigned)gr < (unsigned)HW){
            const float* rp = src + (size_t)gr*HW;
            if (gc0 >= 0 && gc0 + 3 < HW){
                v = *reinterpret_cast<const float4*>(rp + gc0);
                if (z==0){ v.x=sigmoidf_(v.x); v.y=sigmoidf_(v.y); v.z=sigmoidf_(v.z); v.w=sigmoidf_(v.w); }
            } else {
                if (ck0){ float t = rp[gc0+0]; v.x = (z==0)?sigmoidf_(t):t; }
                if (ck1){ float t = rp[gc0+1]; v.y = (z==0)?sigmoidf_(t):t; }
                if (ck2){ float t = rp[gc0+2]; v.z = (z==0)?sigmoidf_(t):t; }
                if (ck3){ float t = rp[gc0+3]; v.w = (z==0)?sigmoidf_(t):t; }
            }
        }
        st4s(A + r*BUFW + c4, v);
    }
    // B boundary rows (never written by erode, read as neighbors)
    if (tid < 64){
        int r = (tid < 32) ? 0 : (BUFH-1);
        st4s(B + r*BUFW + (tid & 31)*4, make_float4(INFV,INFV,INFV,INFV));
    }
    // ---- load other (tile region; 0 outside image) ----
    for (int i = tid; i < TILEH*(OTW/4); i += NT){
        int r  = i / (OTW/4);
        int cc = (i - r*(OTW/4))*4;
        int gr = tr0 + r;
        int gc = tc0 + cc;
        const float* rp = oth + (size_t)gr*HW;
        float4 v;
        if (gc + 3 < HW){
            v = *reinterpret_cast<const float4*>(rp + gc);
            if (z==1){ v.x=sigmoidf_(v.x); v.y=sigmoidf_(v.y); v.z=sigmoidf_(v.z); v.w=sigmoidf_(v.w); }
        } else {
            v.x = (gc+0<HW) ? ((z==1)?sigmoidf_(rp[gc+0]):rp[gc+0]) : 0.f;
            v.y = (gc+1<HW) ? ((z==1)?sigmoidf_(rp[gc+1]):rp[gc+1]) : 0.f;
            v.z = (gc+2<HW) ? ((z==1)?sigmoidf_(rp[gc+2]):rp[gc+2]) : 0.f;
            v.w = (gc+3<HW) ? ((z==1)?sigmoidf_(rp[gc+3]):rp[gc+3]) : 0.f;
        }
        st4s(OT + r*OTW + cc, v);
    }
    __syncthreads();

    // ---- row-strip ownership: rows 1..150 over 16 warps (6x10 + 10x9) ----
    const int r0  = 1 + 9*w + ((w < 6) ? w : 6);
    const int cnt = (w < 6) ? 10 : 9;

    float acc0 = 0.f, acc1 = 0.f;

    #pragma unroll 1
    for (int t = 0; t < 10; t++){
        const float* IMG = (t & 1) ? B : A;
        float*       E   = (t & 1) ? A : B;

        float4 ip = ldrow(IMG, r0-2, c4);
        float4 ic = ldrow(IMG, r0-1, c4);
        float4 h0 = make_float4(NEGB,NEGB,NEGB,NEGB);
        float4 h1 = h0;

        const int steps = cnt + 2;
        for (int s = 0; s < steps; s++){
            const int re = r0 - 1 + s;
            float4 in_ = ldrow(IMG, re+1, c4);

            // ---- erode row re (5-point min), forced +INF outside image ----
            float4 e;
            if (re >= 1 && re <= BUFH-2){
                float4 vm;
                vm.x = fminf(ip.x, fminf(ic.x, in_.x));
                vm.y = fminf(ip.y, fminf(ic.y, in_.y));
                vm.z = fminf(ip.z, fminf(ic.z, in_.z));
                vm.w = fminf(ip.w, fminf(ic.w, in_.w));
                float lf = __shfl_up_sync(0xffffffffu, ic.w, 1);
                float rf = __shfl_down_sync(0xffffffffu, ic.x, 1);
                if (lane == 0)  lf = INFV;
                if (lane == 31) rf = INFV;
                e.x = fminf(vm.x, fminf(lf,   ic.y));
                e.y = fminf(vm.y, fminf(ic.x, ic.z));
                e.z = fminf(vm.z, fminf(ic.y, ic.w));
                e.w = fminf(vm.w, fminf(ic.z, rf));
                const int  gr  = base_r + re;
                const bool rok = (unsigned)gr < (unsigned)HW;
                e.x = (rok && ck0) ? e.x : INFV;
                e.y = (rok && ck1) ? e.y : INFV;
                e.z = (rok && ck2) ? e.z : INFV;
                e.w = (rok && ck3) ? e.w : INFV;
                if (re >= r0 && re < r0 + cnt)
                    st4s(E + re*BUFW + c4, e);
            } else {
                e = make_float4(INFV,INFV,INFV,INFV);
            }

            // ---- guard (INF -> -INF) + horizontal max3 ----
            float4 g;
            g.x = fminf(e.x, 2.0f - e.x);
            g.y = fminf(e.y, 2.0f - e.y);
            g.z = fminf(e.z, 2.0f - e.z);
            g.w = fminf(e.w, 2.0f - e.w);
            float glf = __shfl_up_sync(0xffffffffu, g.w, 1);
            float grf = __shfl_down_sync(0xffffffffu, g.x, 1);
            if (lane == 0)  glf = NEGB;
            if (lane == 31) grf = NEGB;
            float4 h2;
            h2.x = fmaxf(glf, fmaxf(g.x, g.y));
            h2.y = fmaxf(g.x, fmaxf(g.y, g.z));
            h2.z = fmaxf(g.y, fmaxf(g.z, g.w));
            h2.w = fmaxf(g.z, fmaxf(g.w, grf));

            // ---- dilate + skel accumulation for row d = re-1 ----
            const int d = re - 1;
            if (s >= 2 && d >= HALO && d <= HALO+TILEH-1 && lane >= 3 && lane <= 28){
                float4 op;
                op.x = fmaxf(h0.x, fmaxf(h1.x, h2.x));
                op.y = fmaxf(h0.y, fmaxf(h1.y, h2.y));
                op.z = fmaxf(h0.z, fmaxf(h1.z, h2.z));
                op.w = fmaxf(h0.w, fmaxf(h1.w, h2.w));
                float4 ov = ld4s(OT + (d-HALO)*OTW + (c4 - 4*3));
                float rx = fmaxf(ip.x - op.x, 0.f); rx = ck0 ? rx : 0.f;
                float ry = fmaxf(ip.y - op.y, 0.f); ry = ck1 ? ry : 0.f;
                float rz = fmaxf(ip.z - op.z, 0.f); rz = ck2 ? rz : 0.f;
                float rw = fmaxf(ip.w - op.w, 0.f); rw = ck3 ? rw : 0.f;
                acc0 += (rx + ry) + (rz + rw);
                acc1 += rx*ov.x + ry*ov.y + rz*ov.z + rw*ov.w;
            }

            h0 = h1; h1 = h2;
            ip = ic; ic = in_;
        }
        __syncthreads();
    }

    // ---- reduction ----
    #pragma unroll
    for (int off = 16; off; off >>= 1){
        acc0 += __shfl_xor_sync(0xffffffffu, acc0, off);
        acc1 += __shfl_xor_sync(0xffffffffu, acc1, off);
    }
    if (lane == 0){ A[w*2] = acc0; A[w*2+1] = acc1; }
    __syncthreads();
    if (tid < 16){
        float a0 = A[tid*2], a1 = A[tid*2+1];
        #pragma unroll
        for (int off = 8; off; off >>= 1){
            a0 += __shfl_xor_sync(0x0000ffffu, a0, off, 16);
            a1 += __shfl_xor_sync(0x0000ffffu, a1, off, 16);
        }
        if (tid == 0){
            const int base = ((z*32 + img)*NTILES + tile)*2;
            g_part[base + 0] = a0;
            g_part[base + 1] = a1;
        }
    }
}

__global__ void cldice_finalize(float* __restrict__ out){
    const int tid  = threadIdx.x;
    const int im   = tid >> 5;
    const int lane = tid & 31;
    __shared__ float sh[32];
    float S2 = 0.f, S1 = 0.f, S4 = 0.f, S3 = 0.f;
    for (int t = lane; t < NTILES; t += 32){
        const int b0 = ((0*32 + im)*NTILES + t)*2;
        const int b1 = ((1*32 + im)*NTILES + t)*2;
        S2 += g_part[b0 + 0];
        S1 += g_part[b0 + 1];
        S4 += g_part[b1 + 0];
        S3 += g_part[b1 + 1];
    }
    #pragma unroll
    for (int off = 16; off; off >>= 1){
        S2 += __shfl_xor_sync(0xffffffffu, S2, off);
        S1 += __shfl_xor_sync(0xffffffffu, S1, off);
        S4 += __shfl_xor_sync(0xffffffffu, S4, off);
        S3 += __shfl_xor_sync(0xffffffffu, S3, off);
    }
    if (lane == 0){
        const float eps = 1e-6f;
        const float tp = S1 / (S2 + eps);
        const float ts = S3 / (S4 + eps);
        sh[im] = 2.0f*tp*ts / (tp + ts + eps);
    }
    __syncthreads();
    if (tid < 32){
        float c = sh[tid];
        #pragma unroll
        for (int off = 16; off; off >>= 1)
            c += __shfl_xor_sync(0xffffffffu, c, off);
        if (tid == 0)
            out[0] = 1.0f - c * (1.0f/32.0f);
    }
}

extern "C" void kernel_launch(void* const* d_in, const int* in_sizes, int n_in,
                              void* d_out, int out_size){
    const float* logits  = (const float*)d_in[0];
    const float* targets = (const float*)d_in[1];
    float* out = (float*)d_out;

    const int smem = (2*BUFH*BUFW + TILEH*OTW) * (int)sizeof(float);
    cudaFuncSetAttribute(cldice_main, cudaFuncAttributeMaxDynamicSharedMemorySize, smem);

    dim3 grid(NTILES, 32, 2);
    cldice_main<<<grid, NT, smem>>>(logits, targets);
    cldice_finalize<<<1, 1024>>>(out);
}

// round 6
// speedup vs baseline: 2.3517x; 2.3517x over previous
#include <cuda_runtime.h>
#include <cuda_fp16.h>
#include <math.h>

#define HW     1024
#define TILEH  128
#define TILEW  64
#define HALO   12
#define BUFH   152
#define ROWP   104            // halves per row: data cols 0..95, pad 96..103
#define SEGS   12
#define NT     512
#define NTILES 128            // 8 row-tiles x 16 col-tiles
#define INF2U  0x7C007C00u
#define TWO2U  0x40004000u

// per-tile partials: [z][img][tile][{sum_skel, sum_skel*other}]
__device__ float g_part[2*32*NTILES*2];

__device__ __forceinline__ float sigmoidf_(float x){ return 1.0f/(1.0f+__expf(-x)); }
__device__ __forceinline__ unsigned h2u(__half2 h){ return *reinterpret_cast<unsigned*>(&h); }
__device__ __forceinline__ __half2 u2h(unsigned u){ __half2 h; *reinterpret_cast<unsigned*>(&h) = u; return h; }

struct U4 { unsigned x,y,z,w; };
__device__ __forceinline__ U4 ld8h(const __half* p){
    uint4 v = *reinterpret_cast<const uint4*>(p);
    U4 r; r.x=v.x; r.y=v.y; r.z=v.z; r.w=v.w; return r;
}
__device__ __forceinline__ void st8h(__half* p, unsigned a, unsigned b, unsigned c, unsigned d){
    *reinterpret_cast<uint4*>(p) = make_uint4(a,b,c,d);
}

__device__ __forceinline__ unsigned guard_edge(const __half* p){
    __half h = *p;
    __half two = __ushort_as_half((unsigned short)0x4000u);
    __half g = __hmin(h, __hsub(two, h));
    return (unsigned)__half_as_ushort(g);
}

// guarded horizontal max3 of an 8-half row chunk
__device__ __forceinline__ U4 computeH(const __half* E, int row, int cb){
    const __half* p = E + row*ROWP + cb;
    U4 r = ld8h(p);
    unsigned gl = guard_edge(p - 1);
    unsigned gr = guard_edge(p + 8);
    __half2 two = u2h(TWO2U);
    unsigned g0 = h2u(__hmin2(u2h(r.x), __hsub2(two, u2h(r.x))));
    unsigned g1 = h2u(__hmin2(u2h(r.y), __hsub2(two, u2h(r.y))));
    unsigned g2 = h2u(__hmin2(u2h(r.z), __hsub2(two, u2h(r.z))));
    unsigned g3 = h2u(__hmin2(u2h(r.w), __hsub2(two, u2h(r.w))));
    unsigned t0 = __byte_perm(g0, gl, 0x1054);
    unsigned t1 = __byte_perm(g0, g1, 0x5432);
    unsigned t2 = __byte_perm(g1, g2, 0x5432);
    unsigned t3 = __byte_perm(g2, g3, 0x5432);
    unsigned s3 = __byte_perm(g3, gr, 0x5432);
    U4 H;
    H.x = h2u(__hmax2(u2h(t0), __hmax2(u2h(g0), u2h(t1))));
    H.y = h2u(__hmax2(u2h(t1), __hmax2(u2h(g1), u2h(t2))));
    H.z = h2u(__hmax2(u2h(t2), __hmax2(u2h(g2), u2h(t3))));
    H.w = h2u(__hmax2(u2h(t3), __hmax2(u2h(g3), u2h(s3))));
    return H;
}

// vertical max3 + relu(img - opened) accumulate (packed fp16)
__device__ __forceinline__ void outrow(const __half* IMG, int d, int cb,
                                       const U4& X, const U4& Y, const U4& Z,
                                       unsigned* sk){
    U4 im = ld8h(IMG + d*ROWP + cb);
    __half2 zero = u2h(0u);
    __half2 op, inc;
    op  = __hmax2(u2h(X.x), __hmax2(u2h(Y.x), u2h(Z.x)));
    inc = __hmax2(__hsub2(u2h(im.x), op), zero);
    sk[0] = h2u(__hadd2(u2h(sk[0]), inc));
    op  = __hmax2(u2h(X.y), __hmax2(u2h(Y.y), u2h(Z.y)));
    inc = __hmax2(__hsub2(u2h(im.y), op), zero);
    sk[1] = h2u(__hadd2(u2h(sk[1]), inc));
    op  = __hmax2(u2h(X.z), __hmax2(u2h(Y.z), u2h(Z.z)));
    inc = __hmax2(__hsub2(u2h(im.z), op), zero);
    sk[2] = h2u(__hadd2(u2h(sk[2]), inc));
    op  = __hmax2(u2h(X.w), __hmax2(u2h(Y.w), u2h(Z.w)));
    inc = __hmax2(__hsub2(u2h(im.w), op), zero);
    sk[3] = h2u(__hadd2(u2h(sk[3]), inc));
}

__global__ __launch_bounds__(NT, 2)
void cldice_main(const float* __restrict__ logits, const float* __restrict__ targets){
    extern __shared__ __half sh2[];
    __half* A = sh2;
    __half* B = sh2 + BUFH*ROWP;

    const int tid  = threadIdx.x;
    const int tile = blockIdx.x;               // 0..127
    const int img  = blockIdx.y;               // 0..31
    const int z    = blockIdx.z;               // 0: skel(pred), 1: skel(gt)
    const int tr0  = (tile >> 4) * TILEH;
    const int tc0  = (tile & 15) * TILEW;
    const int base_r = tr0 - HALO;
    const size_t ioff = (size_t)img * (HW*HW);
    const float* src = (z==0 ? logits : targets) + ioff;

    // ---- load A: 152 rows x 12 segs of 8 halves (buffer col cb <-> image col tc0+cb-16) ----
    for (int i = tid; i < BUFH*SEGS; i += NT){
        int r = i / SEGS, s = i - r*SEGS;
        int gr = base_r + r;
        int icb = tc0 + 8*s - 16;
        unsigned o0,o1,o2,o3;
        bool rok = (unsigned)gr < (unsigned)HW;
        if (rok && icb >= 0 && icb + 7 < HW){
            const float4* rp = reinterpret_cast<const float4*>(src + (size_t)gr*HW + icb);
            float4 a = rp[0], b4 = rp[1];
            if (z==0){
                a.x=sigmoidf_(a.x); a.y=sigmoidf_(a.y); a.z=sigmoidf_(a.z); a.w=sigmoidf_(a.w);
                b4.x=sigmoidf_(b4.x); b4.y=sigmoidf_(b4.y); b4.z=sigmoidf_(b4.z); b4.w=sigmoidf_(b4.w);
            }
            o0 = h2u(__floats2half2_rn(a.x,a.y));
            o1 = h2u(__floats2half2_rn(a.z,a.w));
            o2 = h2u(__floats2half2_rn(b4.x,b4.y));
            o3 = h2u(__floats2half2_rn(b4.z,b4.w));
        } else {
            unsigned short hh[8];
            #pragma unroll
            for (int k = 0; k < 8; k++){
                int ic = icb + k;
                float v;
                if (rok && (unsigned)ic < (unsigned)HW){
                    v = src[(size_t)gr*HW + ic];
                    if (z==0) v = sigmoidf_(v);
                    hh[k] = __half_as_ushort(__float2half_rn(v));
                } else hh[k] = (unsigned short)0x7C00u;
            }
            o0 = (unsigned)hh[0] | ((unsigned)hh[1]<<16);
            o1 = (unsigned)hh[2] | ((unsigned)hh[3]<<16);
            o2 = (unsigned)hh[4] | ((unsigned)hh[5]<<16);
            o3 = (unsigned)hh[6] | ((unsigned)hh[7]<<16);
        }
        st8h(A + r*ROWP + 8*s, o0,o1,o2,o3);
    }
    // pads cols 96..103 of both buffers; B rows 0 and 151
    for (int r = tid; r < BUFH; r += NT){
        st8h(A + r*ROWP + 96, INF2U,INF2U,INF2U,INF2U);
        st8h(B + r*ROWP + 96, INF2U,INF2U,INF2U,INF2U);
    }
    if (tid < 2*SEGS){
        int r = (tid < SEGS) ? 0 : (BUFH-1);
        int s = tid % SEGS;
        st8h(B + r*ROWP + 8*s, INF2U,INF2U,INF2U,INF2U);
    }
    __syncthreads();

    // ---- erode mapping: 12 segs x 42 row-groups (24x4 + 18x3 = 150 rows) ----
    const int eseg = tid % SEGS;
    const int eg   = tid / SEGS;
    const bool eact = (eg < 42);
    int er0, ecnt;
    if (eg < 24){ er0 = 1 + 4*eg;        ecnt = 4; }
    else        { er0 = 97 + 3*(eg-24);  ecnt = 3; }
    unsigned cm[4];
    {
        int icb = tc0 + 8*eseg - 16;
        #pragma unroll
        for (int m = 0; m < 4; m++){
            int i0 = icb + 2*m;
            unsigned lo = ((unsigned)i0     < (unsigned)HW) ? 0x0000FFFFu : 0u;
            unsigned hi = ((unsigned)(i0+1) < (unsigned)HW) ? 0xFFFF0000u : 0u;
            cm[m] = lo | hi;
        }
    }

    // ---- dilate mapping: 8 segs x 64 groups of 2 rows ----
    const int sd = tid & 7;
    const int gd = tid >> 3;
    const int d0 = HALO + 2*gd;        // 12..138
    const int cb = 16 + 8*sd;          // 16..72

    unsigned sk[8] = {0,0,0,0,0,0,0,0};

    #pragma unroll 1
    for (int t = 0; t < 10; t++){
        const __half* IMG = (t & 1) ? B : A;
        __half*       E   = (t & 1) ? A : B;

        if (eact){
            const __half* rowc = IMG + er0*ROWP + 8*eseg;
            __half*       erow = E   + er0*ROWP + 8*eseg;
            U4 up  = ld8h(rowc - ROWP);
            U4 cur = ld8h(rowc);
            #pragma unroll 1
            for (int k = 0; k < ecnt; k++){
                U4 dn = ld8h(rowc + ROWP);
                unsigned lh = (unsigned)__half_as_ushort(rowc[-1]);
                unsigned rh = (unsigned)__half_as_ushort(rowc[8]);
                __half2 v0 = __hmin2(u2h(up.x), u2h(dn.x));
                __half2 v1 = __hmin2(u2h(up.y), u2h(dn.y));
                __half2 v2 = __hmin2(u2h(up.z), u2h(dn.z));
                __half2 v3 = __hmin2(u2h(up.w), u2h(dn.w));
                unsigned t0 = __byte_perm(cur.x, lh,    0x1054);
                unsigned t1 = __byte_perm(cur.x, cur.y, 0x5432);
                unsigned t2 = __byte_perm(cur.y, cur.z, 0x5432);
                unsigned t3 = __byte_perm(cur.z, cur.w, 0x5432);
                unsigned s3 = __byte_perm(cur.w, rh,    0x5432);
                __half2 h0 = __hmin2(u2h(t0), u2h(t1));
                __half2 h1 = __hmin2(u2h(t1), u2h(t2));
                __half2 h2 = __hmin2(u2h(t2), u2h(t3));
                __half2 h3 = __hmin2(u2h(t3), u2h(s3));
                unsigned e0 = h2u(__hmin2(u2h(cur.x), __hmin2(v0, h0)));
                unsigned e1 = h2u(__hmin2(u2h(cur.y), __hmin2(v1, h1)));
                unsigned e2 = h2u(__hmin2(u2h(cur.z), __hmin2(v2, h2)));
                unsigned e3 = h2u(__hmin2(u2h(cur.w), __hmin2(v3, h3)));
                const bool rok = (unsigned)(base_r + er0 + k) < (unsigned)HW;
                unsigned c0 = rok ? cm[0] : 0u;
                unsigned c1 = rok ? cm[1] : 0u;
                unsigned c2 = rok ? cm[2] : 0u;
                unsigned c3 = rok ? cm[3] : 0u;
                e0 = (e0 & c0) | (INF2U & ~c0);
                e1 = (e1 & c1) | (INF2U & ~c1);
                e2 = (e2 & c2) | (INF2U & ~c2);
                e3 = (e3 & c3) | (INF2U & ~c3);
                st8h(erow, e0,e1,e2,e3);
                up = cur; cur = dn;
                rowc += ROWP; erow += ROWP;
            }
        }
        __syncthreads();

        U4 Ha = computeH(E, d0-1, cb);
        U4 Hb = computeH(E, d0,   cb);
        U4 Hc = computeH(E, d0+1, cb);
        outrow(IMG, d0, cb, Ha, Hb, Hc, sk);
        Ha = computeH(E, d0+2, cb);
        outrow(IMG, d0+1, cb, Hb, Hc, Ha, sk+4);
        __syncthreads();
    }

    // ---- final per-thread accumulation against `other` (from gmem) ----
    float acc0 = 0.f, acc1 = 0.f;
    {
        const float* oth = (z==0 ? targets : logits) + ioff;
        const int gr0 = tr0 + 2*gd;
        const int gc  = tc0 + 8*sd;
        #pragma unroll
        for (int j = 0; j < 2; j++){
            const float4* rp = reinterpret_cast<const float4*>(oth + (size_t)(gr0+j)*HW + gc);
            float4 oA = rp[0], oB = rp[1];
            if (z==1){
                oA.x=sigmoidf_(oA.x); oA.y=sigmoidf_(oA.y); oA.z=sigmoidf_(oA.z); oA.w=sigmoidf_(oA.w);
                oB.x=sigmoidf_(oB.x); oB.y=sigmoidf_(oB.y); oB.z=sigmoidf_(oB.z); oB.w=sigmoidf_(oB.w);
            }
            float2 f0 = __half22float2(u2h(sk[4*j+0]));
            float2 f1 = __half22float2(u2h(sk[4*j+1]));
            float2 f2 = __half22float2(u2h(sk[4*j+2]));
            float2 f3 = __half22float2(u2h(sk[4*j+3]));
            acc0 += (f0.x+f0.y) + (f1.x+f1.y) + (f2.x+f2.y) + (f3.x+f3.y);
            acc1 += f0.x*oA.x + f0.y*oA.y + f1.x*oA.z + f1.y*oA.w
                  + f2.x*oB.x + f2.y*oB.y + f3.x*oB.z + f3.y*oB.w;
        }
    }
    #pragma unroll
    for (int off = 16; off; off >>= 1){
        acc0 += __shfl_xor_sync(0xffffffffu, acc0, off);
        acc1 += __shfl_xor_sync(0xffffffffu, acc1, off);
    }
    float* red = reinterpret_cast<float*>(sh2);
    const int wid = tid >> 5;
    if ((tid & 31) == 0){ red[wid*2] = acc0; red[wid*2+1] = acc1; }
    __syncthreads();
    if (tid < 16){
        float a0 = red[tid*2], a1 = red[tid*2+1];
        #pragma unroll
        for (int off = 8; off; off >>= 1){
            a0 += __shfl_xor_sync(0x0000ffffu, a0, off, 16);
            a1 += __shfl_xor_sync(0x0000ffffu, a1, off, 16);
        }
        if (tid == 0){
            const int base = ((z*32 + img)*NTILES + tile)*2;
            g_part[base + 0] = a0;
            g_part[base + 1] = a1;
        }
    }
}

__global__ void cldice_finalize(float* __restrict__ out){
    const int tid  = threadIdx.x;
    const int im   = tid >> 5;
    const int lane = tid & 31;
    __shared__ float sh[32];
    float S2 = 0.f, S1 = 0.f, S4 = 0.f, S3 = 0.f;
    for (int t = lane; t < NTILES; t += 32){
        const int b0 = ((0*32 + im)*NTILES + t)*2;
        const int b1 = ((1*32 + im)*NTILES + t)*2;
        S2 += g_part[b0 + 0];
        S1 += g_part[b0 + 1];
        S4 += g_part[b1 + 0];
        S3 += g_part[b1 + 1];
    }
    #pragma unroll
    for (int off = 16; off; off >>= 1){
        S2 += __shfl_xor_sync(0xffffffffu, S2, off);
        S1 += __shfl_xor_sync(0xffffffffu, S1, off);
        S4 += __shfl_xor_sync(0xffffffffu, S4, off);
        S3 += __shfl_xor_sync(0xffffffffu, S3, off);
    }
    if (lane == 0){
        const float eps = 1e-6f;
        const float tp = S1 / (S2 + eps);
        const float ts = S3 / (S4 + eps);
        sh[im] = 2.0f*tp*ts / (tp + ts + eps);
    }
    __syncthreads();
    if (tid < 32){
        float c = sh[tid];
        #pragma unroll
        for (int off = 16; off; off >>= 1)
            c += __shfl_xor_sync(0xffffffffu, c, off);
        if (tid == 0)
            out[0] = 1.0f - c * (1.0f/32.0f);
    }
}

extern "C" void kernel_launch(void* const* d_in, const int* in_sizes, int n_in,
                              void* d_out, int out_size){
    const float* logits  = (const float*)d_in[0];
    const float* targets = (const float*)d_in[1];
    float* out = (float*)d_out;

    const int smem = 2*BUFH*ROWP*(int)sizeof(__half);
    cudaFuncSetAttribute(cldice_main, cudaFuncAttributeMaxDynamicSharedMemorySize, smem);

    dim3 grid(NTILES, 32, 2);
    cldice_main<<<grid, NT, smem>>>(logits, targets);
    cldice_finalize<<<1, 1024>>>(out);
}

// round 7
// speedup vs baseline: 2.4849x; 1.0566x over previous
#include <cuda_runtime.h>
#include <cuda_fp16.h>
#include <math.h>

#define HW     1024
#define TILEH  128
#define TILEW  64
#define HALO   12
#define BUFH   152
#define ROWP   104            // halves per row: data cols 0..95, pad 96..103
#define SEGS   12
#define NT     512
#define NTILES 128            // 8 row-tiles x 16 col-tiles
#define INF2U  0x7C007C00u
#define TWO2U  0x40004000u

// per-tile partials: [z][img][tile][{sum_skel, sum_skel*other}]
__device__ float g_part[2*32*NTILES*2];

__device__ __forceinline__ float sigmoidf_(float x){ return 1.0f/(1.0f+__expf(-x)); }
__device__ __forceinline__ unsigned h2u(__half2 h){ return *reinterpret_cast<unsigned*>(&h); }
__device__ __forceinline__ __half2 u2h(unsigned u){ __half2 h; *reinterpret_cast<unsigned*>(&h) = u; return h; }

struct U4 { unsigned x,y,z,w; };
__device__ __forceinline__ U4 ld8h(const __half* p){
    uint4 v = *reinterpret_cast<const uint4*>(p);
    U4 r; r.x=v.x; r.y=v.y; r.z=v.z; r.w=v.w; return r;
}
__device__ __forceinline__ void st8h(__half* p, unsigned a, unsigned b, unsigned c, unsigned d){
    *reinterpret_cast<uint4*>(p) = make_uint4(a,b,c,d);
}

__device__ __forceinline__ unsigned guard_edge(const __half* p){
    __half h = *p;
    __half two = __ushort_as_half((unsigned short)0x4000u);
    __half g = __hmin(h, __hsub(two, h));
    return (unsigned)__half_as_ushort(g);
}

// guarded horizontal max3 of an 8-half row chunk
__device__ __forceinline__ U4 computeH(const __half* E, int row, int cb){
    const __half* p = E + row*ROWP + cb;
    U4 r = ld8h(p);
    unsigned gl = guard_edge(p - 1);
    unsigned gr = guard_edge(p + 8);
    __half2 two = u2h(TWO2U);
    unsigned g0 = h2u(__hmin2(u2h(r.x), __hsub2(two, u2h(r.x))));
    unsigned g1 = h2u(__hmin2(u2h(r.y), __hsub2(two, u2h(r.y))));
    unsigned g2 = h2u(__hmin2(u2h(r.z), __hsub2(two, u2h(r.z))));
    unsigned g3 = h2u(__hmin2(u2h(r.w), __hsub2(two, u2h(r.w))));
    unsigned t0 = __byte_perm(g0, gl, 0x1054);
    unsigned t1 = __byte_perm(g0, g1, 0x5432);
    unsigned t2 = __byte_perm(g1, g2, 0x5432);
    unsigned t3 = __byte_perm(g2, g3, 0x5432);
    unsigned s3 = __byte_perm(g3, gr, 0x5432);
    U4 H;
    H.x = h2u(__hmax2(u2h(t0), __hmax2(u2h(g0), u2h(t1))));
    H.y = h2u(__hmax2(u2h(t1), __hmax2(u2h(g1), u2h(t2))));
    H.z = h2u(__hmax2(u2h(t2), __hmax2(u2h(g2), u2h(t3))));
    H.w = h2u(__hmax2(u2h(t3), __hmax2(u2h(g3), u2h(s3))));
    return H;
}

// vertical max3 + relu(img - opened) accumulate (packed fp16)
__device__ __forceinline__ void outrow(const __half* IMG, int d, int cb,
                                       const U4& X, const U4& Y, const U4& Z,
                                       unsigned* sk){
    U4 im = ld8h(IMG + d*ROWP + cb);
    __half2 zero = u2h(0u);
    __half2 op, inc;
    op  = __hmax2(u2h(X.x), __hmax2(u2h(Y.x), u2h(Z.x)));
    inc = __hmax2(__hsub2(u2h(im.x), op), zero);
    sk[0] = h2u(__hadd2(u2h(sk[0]), inc));
    op  = __hmax2(u2h(X.y), __hmax2(u2h(Y.y), u2h(Z.y)));
    inc = __hmax2(__hsub2(u2h(im.y), op), zero);
    sk[1] = h2u(__hadd2(u2h(sk[1]), inc));
    op  = __hmax2(u2h(X.z), __hmax2(u2h(Y.z), u2h(Z.z)));
    inc = __hmax2(__hsub2(u2h(im.z), op), zero);
    sk[2] = h2u(__hadd2(u2h(sk[2]), inc));
    op  = __hmax2(u2h(X.w), __hmax2(u2h(Y.w), u2h(Z.w)));
    inc = __hmax2(__hsub2(u2h(im.w), op), zero);
    sk[3] = h2u(__hadd2(u2h(sk[3]), inc));
}

__global__ __launch_bounds__(NT, 2)
void cldice_main(const float* __restrict__ logits, const float* __restrict__ targets){
    extern __shared__ __half sh2[];
    __half* W0 = sh2;
    __half* W1 = sh2 +   BUFH*ROWP;
    __half* W2 = sh2 + 2*BUFH*ROWP;

    const int tid  = threadIdx.x;
    const int tile = blockIdx.x;               // 0..127
    const int img  = blockIdx.y;               // 0..31
    const int z    = blockIdx.z;               // 0: skel(pred), 1: skel(gt)
    const int tr0  = (tile >> 4) * TILEH;
    const int tc0  = (tile & 15) * TILEW;
    const int base_r = tr0 - HALO;
    const size_t ioff = (size_t)img * (HW*HW);
    const float* src = (z==0 ? logits : targets) + ioff;

    // ---- load W0: 152 rows x 12 segs of 8 halves (buffer col cb <-> image col tc0+cb-16) ----
    for (int i = tid; i < BUFH*SEGS; i += NT){
        int r = i / SEGS, s = i - r*SEGS;
        int gr = base_r + r;
        int icb = tc0 + 8*s - 16;
        unsigned o0,o1,o2,o3;
        bool rok = (unsigned)gr < (unsigned)HW;
        if (rok && icb >= 0 && icb + 7 < HW){
            const float4* rp = reinterpret_cast<const float4*>(src + (size_t)gr*HW + icb);
            float4 a = rp[0], b4 = rp[1];
            if (z==0){
                a.x=sigmoidf_(a.x); a.y=sigmoidf_(a.y); a.z=sigmoidf_(a.z); a.w=sigmoidf_(a.w);
                b4.x=sigmoidf_(b4.x); b4.y=sigmoidf_(b4.y); b4.z=sigmoidf_(b4.z); b4.w=sigmoidf_(b4.w);
            }
            o0 = h2u(__floats2half2_rn(a.x,a.y));
            o1 = h2u(__floats2half2_rn(a.z,a.w));
            o2 = h2u(__floats2half2_rn(b4.x,b4.y));
            o3 = h2u(__floats2half2_rn(b4.z,b4.w));
        } else {
            unsigned short hh[8];
            #pragma unroll
            for (int k = 0; k < 8; k++){
                int ic = icb + k;
                float v;
                if (rok && (unsigned)ic < (unsigned)HW){
                    v = src[(size_t)gr*HW + ic];
                    if (z==0) v = sigmoidf_(v);
                    hh[k] = __half_as_ushort(__float2half_rn(v));
                } else hh[k] = (unsigned short)0x7C00u;
            }
            o0 = (unsigned)hh[0] | ((unsigned)hh[1]<<16);
            o1 = (unsigned)hh[2] | ((unsigned)hh[3]<<16);
            o2 = (unsigned)hh[4] | ((unsigned)hh[5]<<16);
            o3 = (unsigned)hh[6] | ((unsigned)hh[7]<<16);
        }
        st8h(W0 + r*ROWP + 8*s, o0,o1,o2,o3);
    }
    // pads cols 96..103 of all buffers; W1/W2 boundary rows 0 and 151
    for (int r = tid; r < BUFH; r += NT){
        st8h(W0 + r*ROWP + 96, INF2U,INF2U,INF2U,INF2U);
        st8h(W1 + r*ROWP + 96, INF2U,INF2U,INF2U,INF2U);
        st8h(W2 + r*ROWP + 96, INF2U,INF2U,INF2U,INF2U);
    }
    if (tid < 4*SEGS){
        int which = tid / (2*SEGS);          // 0 -> W1, 1 -> W2
        int rr    = (tid / SEGS) & 1;        // 0 or 1
        int r = rr ? (BUFH-1) : 0;
        int s = tid % SEGS;
        __half* T = which ? W2 : W1;
        st8h(T + r*ROWP + 8*s, INF2U,INF2U,INF2U,INF2U);
    }
    __syncthreads();

    // ---- erode mapping: 12 segs x 42 row-groups (24x4 + 18x3 = 150 rows) ----
    const int eseg = tid % SEGS;
    const int eg   = tid / SEGS;
    const bool eact = (eg < 42);
    int er0, ecnt;
    if (eg < 24){ er0 = 1 + 4*eg;        ecnt = 4; }
    else        { er0 = 97 + 3*(eg-24);  ecnt = 3; }
    unsigned cm[4];
    {
        int icb = tc0 + 8*eseg - 16;
        #pragma unroll
        for (int m = 0; m < 4; m++){
            int i0 = icb + 2*m;
            unsigned lo = ((unsigned)i0     < (unsigned)HW) ? 0x0000FFFFu : 0u;
            unsigned hi = ((unsigned)(i0+1) < (unsigned)HW) ? 0xFFFF0000u : 0u;
            cm[m] = lo | hi;
        }
    }

    // ---- dilate mapping: 8 segs x 64 groups of 2 rows ----
    const int sd = tid & 7;
    const int gd = tid >> 3;
    const int d0 = HALO + 2*gd;        // 12..138
    const int cb = 16 + 8*sd;          // 16..72

    unsigned sk[8] = {0,0,0,0,0,0,0,0};

    __half* IMG = W0;
    __half* E   = W1;
    __half* C   = W2;

    #pragma unroll 1
    for (int t = 0; t < 10; t++){
        if (eact){
            const __half* rowc = IMG + er0*ROWP + 8*eseg;
            __half*       erow = E   + er0*ROWP + 8*eseg;
            U4 up  = ld8h(rowc - ROWP);
            U4 cur = ld8h(rowc);
            #pragma unroll 1
            for (int k = 0; k < ecnt; k++){
                U4 dn = ld8h(rowc + ROWP);
                unsigned lh = (unsigned)__half_as_ushort(rowc[-1]);
                unsigned rh = (unsigned)__half_as_ushort(rowc[8]);
                __half2 v0 = __hmin2(u2h(up.x), u2h(dn.x));
                __half2 v1 = __hmin2(u2h(up.y), u2h(dn.y));
                __half2 v2 = __hmin2(u2h(up.z), u2h(dn.z));
                __half2 v3 = __hmin2(u2h(up.w), u2h(dn.w));
                unsigned t0 = __byte_perm(cur.x, lh,    0x1054);
                unsigned t1 = __byte_perm(cur.x, cur.y, 0x5432);
                unsigned t2 = __byte_perm(cur.y, cur.z, 0x5432);
                unsigned t3 = __byte_perm(cur.z, cur.w, 0x5432);
                unsigned s3 = __byte_perm(cur.w, rh,    0x5432);
                __half2 h0 = __hmin2(u2h(t0), u2h(t1));
                __half2 h1 = __hmin2(u2h(t1), u2h(t2));
                __half2 h2 = __hmin2(u2h(t2), u2h(t3));
                __half2 h3 = __hmin2(u2h(t3), u2h(s3));
                unsigned e0 = h2u(__hmin2(u2h(cur.x), __hmin2(v0, h0)));
                unsigned e1 = h2u(__hmin2(u2h(cur.y), __hmin2(v1, h1)));
                unsigned e2 = h2u(__hmin2(u2h(cur.z), __hmin2(v2, h2)));
                unsigned e3 = h2u(__hmin2(u2h(cur.w), __hmin2(v3, h3)));
                const bool rok = (unsigned)(base_r + er0 + k) < (unsigned)HW;
                unsigned c0 = rok ? cm[0] : 0u;
                unsigned c1 = rok ? cm[1] : 0u;
                unsigned c2 = rok ? cm[2] : 0u;
                unsigned c3 = rok ? cm[3] : 0u;
                e0 = (e0 & c0) | (INF2U & ~c0);
                e1 = (e1 & c1) | (INF2U & ~c1);
                e2 = (e2 & c2) | (INF2U & ~c2);
                e3 = (e3 & c3) | (INF2U & ~c3);
                st8h(erow, e0,e1,e2,e3);
                up = cur; cur = dn;
                rowc += ROWP; erow += ROWP;
            }
        }
        __syncthreads();

        U4 Ha = computeH(E, d0-1, cb);
        U4 Hb = computeH(E, d0,   cb);
        U4 Hc = computeH(E, d0+1, cb);
        outrow(IMG, d0, cb, Ha, Hb, Hc, sk);
        Ha = computeH(E, d0+2, cb);
        outrow(IMG, d0+1, cb, Hb, Hc, Ha, sk+4);

        // rotate triple buffer: next IMG = E, next E = C, next C = old IMG
        __half* tmp = IMG;
        IMG = E; E = C; C = tmp;
    }
    __syncthreads();   // all reads done before reusing sh2 for reduction

    // ---- final per-thread accumulation against `other` (from gmem) ----
    float acc0 = 0.f, acc1 = 0.f;
    {
        const float* oth = (z==0 ? targets : logits) + ioff;
        const int gr0 = tr0 + 2*gd;
        const int gc  = tc0 + 8*sd;
        #pragma unroll
        for (int j = 0; j < 2; j++){
            const float4* rp = reinterpret_cast<const float4*>(oth + (size_t)(gr0+j)*HW + gc);
            float4 oA = rp[0], oB = rp[1];
            if (z==1){
                oA.x=sigmoidf_(oA.x); oA.y=sigmoidf_(oA.y); oA.z=sigmoidf_(oA.z); oA.w=sigmoidf_(oA.w);
                oB.x=sigmoidf_(oB.x); oB.y=sigmoidf_(oB.y); oB.z=sigmoidf_(oB.z); oB.w=sigmoidf_(oB.w);
            }
            float2 f0 = __half22float2(u2h(sk[4*j+0]));
            float2 f1 = __half22float2(u2h(sk[4*j+1]));
            float2 f2 = __half22float2(u2h(sk[4*j+2]));
            float2 f3 = __half22float2(u2h(sk[4*j+3]));
            acc0 += (f0.x+f0.y) + (f1.x+f1.y) + (f2.x+f2.y) + (f3.x+f3.y);
            acc1 += f0.x*oA.x + f0.y*oA.y + f1.x*oA.z + f1.y*oA.w
                  + f2.x*oB.x + f2.y*oB.y + f3.x*oB.z + f3.y*oB.w;
        }
    }
    #pragma unroll
    for (int off = 16; off; off >>= 1){
        acc0 += __shfl_xor_sync(0xffffffffu, acc0, off);
        acc1 += __shfl_xor_sync(0xffffffffu, acc1, off);
    }
    float* red = reinterpret_cast<float*>(sh2);
    const int wid = tid >> 5;
    if ((tid & 31) == 0){ red[wid*2] = acc0; red[wid*2+1] = acc1; }
    __syncthreads();
    if (tid < 16){
        float a0 = red[tid*2], a1 = red[tid*2+1];
        #pragma unroll
        for (int off = 8; off; off >>= 1){
            a0 += __shfl_xor_sync(0x0000ffffu, a0, off, 16);
            a1 += __shfl_xor_sync(0x0000ffffu, a1, off, 16);
        }
        if (tid == 0){
            const int base = ((z*32 + img)*NTILES + tile)*2;
            g_part[base + 0] = a0;
            g_part[base + 1] = a1;
        }
    }
}

__global__ void cldice_finalize(float* __restrict__ out){
    const int tid  = threadIdx.x;
    const int im   = tid >> 5;
    const int lane = tid & 31;
    __shared__ float sh[32];
    float S2 = 0.f, S1 = 0.f, S4 = 0.f, S3 = 0.f;
    for (int t = lane; t < NTILES; t += 32){
        const int b0 = ((0*32 + im)*NTILES + t)*2;
        const int b1 = ((1*32 + im)*NTILES + t)*2;
        S2 += g_part[b0 + 0];
        S1 += g_part[b0 + 1];
        S4 += g_part[b1 + 0];
        S3 += g_part[b1 + 1];
    }
    #pragma unroll
    for (int off = 16; off; off >>= 1){
        S2 += __shfl_xor_sync(0xffffffffu, S2, off);
        S1 += __shfl_xor_sync(0xffffffffu, S1, off);
        S4 += __shfl_xor_sync(0xffffffffu, S4, off);
        S3 += __shfl_xor_sync(0xffffffffu, S3, off);
    }
    if (lane == 0){
        const float eps = 1e-6f;
        const float tp = S1 / (S2 + eps);
        const float ts = S3 / (S4 + eps);
        sh[im] = 2.0f*tp*ts / (tp + ts + eps);
    }
    __syncthreads();
    if (tid < 32){
        float c = sh[tid];
        #pragma unroll
        for (int off = 16; off; off >>= 1)
            c += __shfl_xor_sync(0xffffffffu, c, off);
        if (tid == 0)
            out[0] = 1.0f - c * (1.0f/32.0f);
    }
}

extern "C" void kernel_launch(void* const* d_in, const int* in_sizes, int n_in,
                              void* d_out, int out_size){
    const float* logits  = (const float*)d_in[0];
    const float* targets = (const float*)d_in[1];
    float* out = (float*)d_out;

    const int smem = 3*BUFH*ROWP*(int)sizeof(__half);
    cudaFuncSetAttribute(cldice_main, cudaFuncAttributeMaxDynamicSharedMemorySize, smem);

    dim3 grid(NTILES, 32, 2);
    cldice_main<<<grid, NT, smem>>>(logits, targets);
    cldice_finalize<<<1, 1024>>>(out);
}

// round 8
// speedup vs baseline: 2.6689x; 1.0740x over previous
#include <cuda_runtime.h>
#include <cuda_fp16.h>
#include <math.h>

#define HW     1024
#define TILEH  128
#define TILEW  64
#define HALO   12
#define BUFH   152
#define ROWP   104            // halves per row: data cols 0..95, pad 96..103
#define SEGS   12
#define NT     384
#define NTILES 128            // 8 row-tiles x 16 col-tiles
#define INF2U  0x7C007C00u
#define TWO2U  0x40004000u

// per-tile partials: [z][img][tile][{sum_skel, sum_skel*other}]
__device__ float g_part[2*32*NTILES*2];

__device__ __forceinline__ float sigmoidf_(float x){ return 1.0f/(1.0f+__expf(-x)); }
__device__ __forceinline__ unsigned h2u(__half2 h){ return *reinterpret_cast<unsigned*>(&h); }
__device__ __forceinline__ __half2 u2h(unsigned u){ __half2 h; *reinterpret_cast<unsigned*>(&h) = u; return h; }

struct U4 { unsigned x,y,z,w; };
__device__ __forceinline__ U4 ld8h(const __half* p){
    uint4 v = *reinterpret_cast<const uint4*>(p);
    U4 r; r.x=v.x; r.y=v.y; r.z=v.z; r.w=v.w; return r;
}
__device__ __forceinline__ void st8h(__half* p, unsigned a, unsigned b, unsigned c, unsigned d){
    *reinterpret_cast<uint4*>(p) = make_uint4(a,b,c,d);
}

__device__ __forceinline__ unsigned guard_edge(const __half* p){
    __half h = *p;
    __half two = __ushort_as_half((unsigned short)0x4000u);
    __half g = __hmin(h, __hsub(two, h));
    return (unsigned)__half_as_ushort(g);
}

// guarded horizontal max3 of an 8-half row chunk
__device__ __forceinline__ U4 computeH(const __half* E, int row, int cb){
    const __half* p = E + row*ROWP + cb;
    U4 r = ld8h(p);
    unsigned gl = guard_edge(p - 1);
    unsigned gr = guard_edge(p + 8);
    __half2 two = u2h(TWO2U);
    unsigned g0 = h2u(__hmin2(u2h(r.x), __hsub2(two, u2h(r.x))));
    unsigned g1 = h2u(__hmin2(u2h(r.y), __hsub2(two, u2h(r.y))));
    unsigned g2 = h2u(__hmin2(u2h(r.z), __hsub2(two, u2h(r.z))));
    unsigned g3 = h2u(__hmin2(u2h(r.w), __hsub2(two, u2h(r.w))));
    unsigned t0 = __byte_perm(g0, gl, 0x1054);
    unsigned t1 = __byte_perm(g0, g1, 0x5432);
    unsigned t2 = __byte_perm(g1, g2, 0x5432);
    unsigned t3 = __byte_perm(g2, g3, 0x5432);
    unsigned s3 = __byte_perm(g3, gr, 0x5432);
    U4 H;
    H.x = h2u(__hmax2(u2h(t0), __hmax2(u2h(g0), u2h(t1))));
    H.y = h2u(__hmax2(u2h(t1), __hmax2(u2h(g1), u2h(t2))));
    H.z = h2u(__hmax2(u2h(t2), __hmax2(u2h(g2), u2h(t3))));
    H.w = h2u(__hmax2(u2h(t3), __hmax2(u2h(g3), u2h(s3))));
    return H;
}

// vertical max3 + relu(img - opened) accumulate (packed fp16)
__device__ __forceinline__ void outrow(const __half* IMG, int d, int cb,
                                       const U4& X, const U4& Y, const U4& Z,
                                       unsigned* sk){
    U4 im = ld8h(IMG + d*ROWP + cb);
    __half2 zero = u2h(0u);
    __half2 op, inc;
    op  = __hmax2(u2h(X.x), __hmax2(u2h(Y.x), u2h(Z.x)));
    inc = __hmax2(__hsub2(u2h(im.x), op), zero);
    sk[0] = h2u(__hadd2(u2h(sk[0]), inc));
    op  = __hmax2(u2h(X.y), __hmax2(u2h(Y.y), u2h(Z.y)));
    inc = __hmax2(__hsub2(u2h(im.y), op), zero);
    sk[1] = h2u(__hadd2(u2h(sk[1]), inc));
    op  = __hmax2(u2h(X.z), __hmax2(u2h(Y.z), u2h(Z.z)));
    inc = __hmax2(__hsub2(u2h(im.z), op), zero);
    sk[2] = h2u(__hadd2(u2h(sk[2]), inc));
    op  = __hmax2(u2h(X.w), __hmax2(u2h(Y.w), u2h(Z.w)));
    inc = __hmax2(__hsub2(u2h(im.w), op), zero);
    sk[3] = h2u(__hadd2(u2h(sk[3]), inc));
}

__global__ __launch_bounds__(NT, 2)
void cldice_main(const float* __restrict__ logits, const float* __restrict__ targets){
    extern __shared__ __half sh2[];
    __half* W0 = sh2;
    __half* W1 = sh2 +   BUFH*ROWP;
    __half* W2 = sh2 + 2*BUFH*ROWP;

    const int tid  = threadIdx.x;
    const int tile = blockIdx.x;               // 0..127
    const int img  = blockIdx.y;               // 0..31
    const int z    = blockIdx.z;               // 0: skel(pred), 1: skel(gt)
    const int tr0  = (tile >> 4) * TILEH;
    const int tc0  = (tile & 15) * TILEW;
    const int base_r = tr0 - HALO;
    const size_t ioff = (size_t)img * (HW*HW);
    const float* src = (z==0 ? logits : targets) + ioff;

    const bool interior = (base_r >= 0) && (base_r + BUFH <= HW)
                       && (tc0 >= 16) && (tc0 + 95 - 16 < HW);

    // ---- load W0: 152 rows x 12 segs of 8 halves (buffer col c <-> image col tc0+c-16) ----
    for (int i = tid; i < BUFH*SEGS; i += NT){
        int r = i / SEGS, s = i - r*SEGS;
        int gr = base_r + r;
        int icb = tc0 + 8*s - 16;
        unsigned o0,o1,o2,o3;
        bool rok = (unsigned)gr < (unsigned)HW;
        if (rok && icb >= 0 && icb + 7 < HW){
            const float4* rp = reinterpret_cast<const float4*>(src + (size_t)gr*HW + icb);
            float4 a = rp[0], b4 = rp[1];
            if (z==0){
                a.x=sigmoidf_(a.x); a.y=sigmoidf_(a.y); a.z=sigmoidf_(a.z); a.w=sigmoidf_(a.w);
                b4.x=sigmoidf_(b4.x); b4.y=sigmoidf_(b4.y); b4.z=sigmoidf_(b4.z); b4.w=sigmoidf_(b4.w);
            }
            o0 = h2u(__floats2half2_rn(a.x,a.y));
            o1 = h2u(__floats2half2_rn(a.z,a.w));
            o2 = h2u(__floats2half2_rn(b4.x,b4.y));
            o3 = h2u(__floats2half2_rn(b4.z,b4.w));
        } else {
            unsigned short hh[8];
            #pragma unroll
            for (int k = 0; k < 8; k++){
                int ic = icb + k;
                float v;
                if (rok && (unsigned)ic < (unsigned)HW){
                    v = src[(size_t)gr*HW + ic];
                    if (z==0) v = sigmoidf_(v);
                    hh[k] = __half_as_ushort(__float2half_rn(v));
                } else hh[k] = (unsigned short)0x7C00u;
            }
            o0 = (unsigned)hh[0] | ((unsigned)hh[1]<<16);
            o1 = (unsigned)hh[2] | ((unsigned)hh[3]<<16);
            o2 = (unsigned)hh[4] | ((unsigned)hh[5]<<16);
            o3 = (unsigned)hh[6] | ((unsigned)hh[7]<<16);
        }
        st8h(W0 + r*ROWP + 8*s, o0,o1,o2,o3);
    }
    // pads cols 96..103 of all buffers (act as +INF right/left neighbors)
    for (int r = tid; r < BUFH; r += NT){
        st8h(W0 + r*ROWP + 96, INF2U,INF2U,INF2U,INF2U);
        st8h(W1 + r*ROWP + 96, INF2U,INF2U,INF2U,INF2U);
        st8h(W2 + r*ROWP + 96, INF2U,INF2U,INF2U,INF2U);
    }
    __syncthreads();

    // ---- erode mapping: 12 segs x 32 row-groups (22x5 + 10x4 = 150 rows) = 384 threads ----
    const int eseg = tid % SEGS;
    const int eg   = tid / SEGS;          // 0..31
    int er0, ecnt;
    if (eg < 22){ er0 = 1 + 5*eg;          ecnt = 5; }
    else        { er0 = 111 + 4*(eg-22);   ecnt = 4; }
    const bool segmid = (eseg >= 1 && eseg <= 10);
    unsigned cm[4];
    {
        int icb = tc0 + 8*eseg - 16;
        #pragma unroll
        for (int m = 0; m < 4; m++){
            int i0 = icb + 2*m;
            unsigned lo = ((unsigned)i0     < (unsigned)HW) ? 0x0000FFFFu : 0u;
            unsigned hi = ((unsigned)(i0+1) < (unsigned)HW) ? 0xFFFF0000u : 0u;
            cm[m] = lo | hi;
        }
    }

    // ---- dilate mapping: 8 segs x 32 groups of 4 rows = 256 threads ----
    const int sd = tid & 7;
    const int gd = tid >> 3;            // 0..47, active < 32
    const bool dact = (tid < 256);
    const int d0 = HALO + 4*gd;         // 12..136
    const int cb = 16 + 8*sd;           // 16..72

    unsigned sk[16];
    #pragma unroll
    for (int i = 0; i < 16; i++) sk[i] = 0u;

    __half* IMG = W0;
    __half* E   = W1;
    __half* C   = W2;

    #pragma unroll 1
    for (int t = 0; t < 10; t++){
        // erode over shrinking region rows [2+t, 149-t], cols [6+t, 89-t]
        const int r_lo = 2 + t, r_hi = 149 - t;
        if (segmid || t <= 1){
            int k0 = r_lo - er0; if (k0 < 0) k0 = 0;
            int k1 = r_hi - er0; if (k1 > ecnt-1) k1 = ecnt-1;
            if (k0 <= k1){
                const __half* rowc = IMG + (er0+k0)*ROWP + 8*eseg;
                __half*       erow = E   + (er0+k0)*ROWP + 8*eseg;
                U4 up  = ld8h(rowc - ROWP);
                U4 cur = ld8h(rowc);
                if (interior){
                    #pragma unroll 1
                    for (int k = k0; k <= k1; k++){
                        U4 dn = ld8h(rowc + ROWP);
                        unsigned lh = (unsigned)__half_as_ushort(rowc[-1]);
                        unsigned rh = (unsigned)__half_as_ushort(rowc[8]);
                        __half2 v0 = __hmin2(u2h(up.x), u2h(dn.x));
                        __half2 v1 = __hmin2(u2h(up.y), u2h(dn.y));
                        __half2 v2 = __hmin2(u2h(up.z), u2h(dn.z));
                        __half2 v3 = __hmin2(u2h(up.w), u2h(dn.w));
                        unsigned t0 = __byte_perm(cur.x, lh,    0x1054);
                        unsigned t1 = __byte_perm(cur.x, cur.y, 0x5432);
                        unsigned t2 = __byte_perm(cur.y, cur.z, 0x5432);
                        unsigned t3 = __byte_perm(cur.z, cur.w, 0x5432);
                        unsigned s3 = __byte_perm(cur.w, rh,    0x5432);
                        __half2 h0 = __hmin2(u2h(t0), u2h(t1));
                        __half2 h1 = __hmin2(u2h(t1), u2h(t2));
                        __half2 h2 = __hmin2(u2h(t2), u2h(t3));
                        __half2 h3 = __hmin2(u2h(t3), u2h(s3));
                        unsigned e0 = h2u(__hmin2(u2h(cur.x), __hmin2(v0, h0)));
                        unsigned e1 = h2u(__hmin2(u2h(cur.y), __hmin2(v1, h1)));
                        unsigned e2 = h2u(__hmin2(u2h(cur.z), __hmin2(v2, h2)));
                        unsigned e3 = h2u(__hmin2(u2h(cur.w), __hmin2(v3, h3)));
                        st8h(erow, e0,e1,e2,e3);
                        up = cur; cur = dn;
                        rowc += ROWP; erow += ROWP;
                    }
                } else {
                    #pragma unroll 1
                    for (int k = k0; k <= k1; k++){
                        U4 dn = ld8h(rowc + ROWP);
                        unsigned lh = (unsigned)__half_as_ushort(rowc[-1]);
                        unsigned rh = (unsigned)__half_as_ushort(rowc[8]);
                        __half2 v0 = __hmin2(u2h(up.x), u2h(dn.x));
                        __half2 v1 = __hmin2(u2h(up.y), u2h(dn.y));
                        __half2 v2 = __hmin2(u2h(up.z), u2h(dn.z));
                        __half2 v3 = __hmin2(u2h(up.w), u2h(dn.w));
                        unsigned t0 = __byte_perm(cur.x, lh,    0x1054);
                        unsigned t1 = __byte_perm(cur.x, cur.y, 0x5432);
                        unsigned t2 = __byte_perm(cur.y, cur.z, 0x5432);
                        unsigned t3 = __byte_perm(cur.z, cur.w, 0x5432);
                        unsigned s3 = __byte_perm(cur.w, rh,    0x5432);
                        __half2 h0 = __hmin2(u2h(t0), u2h(t1));
                        __half2 h1 = __hmin2(u2h(t1), u2h(t2));
                        __half2 h2 = __hmin2(u2h(t2), u2h(t3));
                        __half2 h3 = __hmin2(u2h(t3), u2h(s3));
                        unsigned e0 = h2u(__hmin2(u2h(cur.x), __hmin2(v0, h0)));
                        unsigned e1 = h2u(__hmin2(u2h(cur.y), __hmin2(v1, h1)));
                        unsigned e2 = h2u(__hmin2(u2h(cur.z), __hmin2(v2, h2)));
                        unsigned e3 = h2u(__hmin2(u2h(cur.w), __hmin2(v3, h3)));
                        const bool rok = (unsigned)(base_r + er0 + k) < (unsigned)HW;
                        unsigned c0 = rok ? cm[0] : 0u;
                        unsigned c1 = rok ? cm[1] : 0u;
                        unsigned c2 = rok ? cm[2] : 0u;
                        unsigned c3 = rok ? cm[3] : 0u;
                        e0 = (e0 & c0) | (INF2U & ~c0);
                        e1 = (e1 & c1) | (INF2U & ~c1);
                        e2 = (e2 & c2) | (INF2U & ~c2);
                        e3 = (e3 & c3) | (INF2U & ~c3);
                        st8h(erow, e0,e1,e2,e3);
                        up = cur; cur = dn;
                        rowc += ROWP; erow += ROWP;
                    }
                }
            }
        }
        __syncthreads();

        // dilate(E) + skel accumulation: 4 rows per thread, 6 H-rows rolling
        if (dact){
            U4 h0 = computeH(E, d0-1, cb);
            U4 h1 = computeH(E, d0,   cb);
            U4 h2 = computeH(E, d0+1, cb);
            outrow(IMG, d0,   cb, h0, h1, h2, sk);
            h0 = computeH(E, d0+2, cb);
            outrow(IMG, d0+1, cb, h1, h2, h0, sk+4);
            h1 = computeH(E, d0+3, cb);
            outrow(IMG, d0+2, cb, h2, h0, h1, sk+8);
            h2 = computeH(E, d0+4, cb);
            outrow(IMG, d0+3, cb, h0, h1, h2, sk+12);
        }

        // rotate triple buffer
        __half* tmp = IMG;
        IMG = E; E = C; C = tmp;
    }
    __syncthreads();

    // ---- final per-thread accumulation against `other` (from gmem) ----
    float acc0 = 0.f, acc1 = 0.f;
    if (dact){
        const float* oth = (z==0 ? targets : logits) + ioff;
        const int gr0 = tr0 + 4*gd;
        const int gc  = tc0 + 8*sd;
        #pragma unroll
        for (int j = 0; j < 4; j++){
            const float4* rp = reinterpret_cast<const float4*>(oth + (size_t)(gr0+j)*HW + gc);
            float4 oA = rp[0], oB = rp[1];
            if (z==1){
                oA.x=sigmoidf_(oA.x); oA.y=sigmoidf_(oA.y); oA.z=sigmoidf_(oA.z); oA.w=sigmoidf_(oA.w);
                oB.x=sigmoidf_(oB.x); oB.y=sigmoidf_(oB.y); oB.z=sigmoidf_(oB.z); oB.w=sigmoidf_(oB.w);
            }
            float2 f0 = __half22float2(u2h(sk[4*j+0]));
            float2 f1 = __half22float2(u2h(sk[4*j+1]));
            float2 f2 = __half22float2(u2h(sk[4*j+2]));
            float2 f3 = __half22float2(u2h(sk[4*j+3]));
            acc0 += (f0.x+f0.y) + (f1.x+f1.y) + (f2.x+f2.y) + (f3.x+f3.y);
            acc1 += f0.x*oA.x + f0.y*oA.y + f1.x*oA.z + f1.y*oA.w
                  + f2.x*oB.x + f2.y*oB.y + f3.x*oB.z + f3.y*oB.w;
        }
    }
    #pragma unroll
    for (int off = 16; off; off >>= 1){
        acc0 += __shfl_xor_sync(0xffffffffu, acc0, off);
        acc1 += __shfl_xor_sync(0xffffffffu, acc1, off);
    }
    float* red = reinterpret_cast<float*>(sh2);
    const int wid = tid >> 5;
    if ((tid & 31) == 0){ red[wid*2] = acc0; red[wid*2+1] = acc1; }
    __syncthreads();
    if (tid < 16){
        float a0 = (tid < 12) ? red[tid*2]   : 0.f;
        float a1 = (tid < 12) ? red[tid*2+1] : 0.f;
        #pragma unroll
        for (int off = 8; off; off >>= 1){
            a0 += __shfl_xor_sync(0x0000ffffu, a0, off, 16);
            a1 += __shfl_xor_sync(0x0000ffffu, a1, off, 16);
        }
        if (tid == 0){
            const int base = ((z*32 + img)*NTILES + tile)*2;
            g_part[base + 0] = a0;
            g_part[base + 1] = a1;
        }
    }
}

__global__ void cldice_finalize(float* __restrict__ out){
    const int tid  = threadIdx.x;
    const int im   = tid >> 5;
    const int lane = tid & 31;
    __shared__ float sh[32];
    float S2 = 0.f, S1 = 0.f, S4 = 0.f, S3 = 0.f;
    for (int t = lane; t < NTILES; t += 32){
        const int b0 = ((0*32 + im)*NTILES + t)*2;
        const int b1 = ((1*32 + im)*NTILES + t)*2;
        S2 += g_part[b0 + 0];
        S1 += g_part[b0 + 1];
        S4 += g_part[b1 + 0];
        S3 += g_part[b1 + 1];
    }
    #pragma unroll
    for (int off = 16; off; off >>= 1){
        S2 += __shfl_xor_sync(0xffffffffu, S2, off);
        S1 += __shfl_xor_sync(0xffffffffu, S1, off);
        S4 += __shfl_xor_sync(0xffffffffu, S4, off);
        S3 += __shfl_xor_sync(0xffffffffu, S3, off);
    }
    if (lane == 0){
        const float eps = 1e-6f;
        const float tp = S1 / (S2 + eps);
        const float ts = S3 / (S4 + eps);
        sh[im] = 2.0f*tp*ts / (tp + ts + eps);
    }
    __syncthreads();
    if (tid < 32){
        float c = sh[tid];
        #pragma unroll
        for (int off = 16; off; off >>= 1)
            c += __shfl_xor_sync(0xffffffffu, c, off);
        if (tid == 0)
            out[0] = 1.0f - c * (1.0f/32.0f);
    }
}

extern "C" void kernel_launch(void* const* d_in, const int* in_sizes, int n_in,
                              void* d_out, int out_size){
    const float* logits  = (const float*)d_in[0];
    const float* targets = (const float*)d_in[1];
    float* out = (float*)d_out;

    const int smem = 3*BUFH*ROWP*(int)sizeof(__half);
    cudaFuncSetAttribute(cldice_main, cudaFuncAttributeMaxDynamicSharedMemorySize, smem);

    dim3 grid(NTILES, 32, 2);
    cldice_main<<<grid, NT, smem>>>(logits, targets);
    cldice_finalize<<<1, 1024>>>(out);
}